// round 15
// baseline (speedup 1.0000x reference)
#include <cuda_runtime.h>
#include <cuda_bf16.h>

#define NN 100000
#define NE 1600000
#define FIN 128
#define DH 32        // D*H
#define GH 64
#define HH 16
#define NOUT 10
#define NBLK 391     // (NN+255)/256

// ---------------- scratch (device globals; zero-initialized at module load) ----------------
__device__ __align__(16) float g_x0[NN * DH];         // h / xs (in-place)
__device__ __align__(16) float g_y[NN * DH];          // rdeg_s * R(theta_s) * xs  (per layer)
__device__ __align__(16) float g_m0[NN * GH];
__device__ __align__(16) float g_m1[NN * GH];
__device__ __align__(16) float g_agg64[NN * GH];      // zero at launch start (consumers re-zero)
__device__ __align__(16) float g_agg32[NN * DH];      // same invariant
__device__ __align__(16) float4 g_node[NN];           // (cos, sin, rdeg, 0)
__device__ int g_src[NE];                              // unsorted
__device__ int g_dst[NE];
__device__ __align__(8) int2 g_sdS[NE];                // (src,dst) sorted by dst
__device__ int g_cnt[NN];
__device__ int g_rowptr[NN];
__device__ int g_cursor[NN];
__device__ int g_bsum[NBLK];
__device__ int g_bsumx[NBLK];
__device__ int g_idx64;

// ---------------- helpers ----------------
__device__ __forceinline__ float gelu_f(float v) {
    const float c = 0.7978845608028654f;
    float t = tanhf(c * (v + 0.044715f * v * v * v));
    return 0.5f * v * (1.0f + t);
}

__device__ __forceinline__ void red4(float* p, float4 v) {
    atomicAdd(reinterpret_cast<float4*>(p), v);
}

__device__ __forceinline__ float4 shfl_down4(float4 v, int off) {
    float4 r;
    r.x = __shfl_down_sync(0xffffffffu, v.x, off);
    r.y = __shfl_down_sync(0xffffffffu, v.y, off);
    r.z = __shfl_down_sync(0xffffffffu, v.z, off);
    r.w = __shfl_down_sync(0xffffffffu, v.w, off);
    return r;
}

__device__ __forceinline__ float4 shfl_xor4(float4 v, int msk) {
    float4 r;
    r.x = __shfl_xor_sync(0xffffffffu, v.x, msk);
    r.y = __shfl_xor_sync(0xffffffffu, v.y, msk);
    r.z = __shfl_xor_sync(0xffffffffu, v.z, msk);
    r.w = __shfl_xor_sync(0xffffffffu, v.w, msk);
    return r;
}

// ---------------- init: zero degree counts; probe edge dtype ----------------
__global__ void k_init(const unsigned int* __restrict__ ei_words) {
    int i = blockIdx.x * blockDim.x + threadIdx.x;
    if (i < NN) g_cnt[i] = 0;
    if (i == 0) {
        int is64 = 1;
        for (int k = 0; k < 256; k++)
            if (ei_words[2 * k + 1] != 0u) { is64 = 0; break; }
        g_idx64 = is64;
    }
}

// ---------------- prep: decode indices, count in-degree ----------------
__global__ void k_prep(const void* __restrict__ ei) {
    int e = blockIdx.x * blockDim.x + threadIdx.x;
    if (e >= NE) return;
    int s, d;
    if (g_idx64) {
        const long long* p = (const long long*)ei;
        s = (int)p[e]; d = (int)p[NE + e];
    } else {
        const int* p = (const int*)ei;
        s = p[e]; d = p[NE + e];
    }
    s = min(max(s, 0), NN - 1);
    d = min(max(d, 0), NN - 1);
    g_src[e] = s;
    g_dst[e] = d;
    atomicAdd(&g_cnt[d], 1);
}

// ---------------- counting-sort scans ----------------
__global__ void k_scan1() {
    __shared__ int sm[256];
    int t = threadIdx.x;
    int i = blockIdx.x * 256 + t;
    int v = (i < NN) ? g_cnt[i] : 0;
    sm[t] = v;
    __syncthreads();
    for (int off = 1; off < 256; off <<= 1) {
        int x = (t >= off) ? sm[t - off] : 0;
        __syncthreads();
        sm[t] += x;
        __syncthreads();
    }
    if (i < NN) g_rowptr[i] = sm[t] - v;
    if (t == 255) g_bsum[blockIdx.x] = sm[255];
}

__global__ void k_scan2() {
    __shared__ int sm[512];
    int t = threadIdx.x;
    int v = (t < NBLK) ? g_bsum[t] : 0;
    sm[t] = v;
    __syncthreads();
    for (int off = 1; off < 512; off <<= 1) {
        int x = (t >= off) ? sm[t - off] : 0;
        __syncthreads();
        sm[t] += x;
        __syncthreads();
    }
    if (t < NBLK) g_bsumx[t] = sm[t] - v;
}

__global__ void k_scan3() {
    int i = blockIdx.x * blockDim.x + threadIdx.x;
    if (i < NN) {
        int rp = g_rowptr[i] + g_bsumx[i >> 8];
        g_cursor[i] = rp;
    }
}

__global__ void k_place() {
    int e = blockIdx.x * blockDim.x + threadIdx.x;
    if (e >= NE) return;
    int d = g_dst[e];
    int pos = atomicAdd(&g_cursor[d], 1);
    g_sdS[pos] = make_int2(g_src[e], d);
}

// ---------------- embed v3: 4 nodes/warp, 32 nodes/block (measured 69us) ----------------
__global__ __launch_bounds__(256) void k_embed(
    const float* __restrict__ x, const float* __restrict__ W_in,
    const float* __restrict__ b_in, const float* __restrict__ W2,
    const float* __restrict__ b2)
{
    __shared__ float sx[32][FIN];
    __shared__ float sh[32][DH + 1];
    int tid = threadIdx.x;
    int base = blockIdx.x * 32;

    {
        int nl = tid >> 3;
        int nc = min(base + nl, NN - 1);
        const float4* xr = (const float4*)(x + (size_t)nc * FIN);
        float4* sxr = (float4*)&sx[nl][(tid & 7) * 16];
        #pragma unroll
        for (int j = 0; j < 4; j++) sxr[j] = xr[(tid & 7) * 4 + j];
    }
    __syncthreads();

    int w = tid >> 5;
    int t = tid & 31;
    {
        float acc0 = 0.f, acc1 = 0.f, acc2 = 0.f, acc3 = 0.f;
        #pragma unroll 4
        for (int k = 0; k < FIN; k++) {
            float wv = W_in[k * DH + t];
            acc0 = fmaf(sx[4 * w + 0][k], wv, acc0);
            acc1 = fmaf(sx[4 * w + 1][k], wv, acc1);
            acc2 = fmaf(sx[4 * w + 2][k], wv, acc2);
            acc3 = fmaf(sx[4 * w + 3][k], wv, acc3);
        }
        float bv = b_in[t];
        acc0 += bv; acc1 += bv; acc2 += bv; acc3 += bv;
        sh[4 * w + 0][t] = acc0;
        sh[4 * w + 1][t] = acc1;
        sh[4 * w + 2][t] = acc2;
        sh[4 * w + 3][t] = acc3;
        #pragma unroll
        for (int j = 0; j < 4; j++) {
            int n = base + 4 * w + j;
            float v = (j == 0) ? acc0 : (j == 1) ? acc1 : (j == 2) ? acc2 : acc3;
            if (n < NN) g_x0[n * DH + t] = v;
        }
    }
    __syncthreads();

    {
        float a0x = 0.f, a0y = 0.f, a1x = 0.f, a1y = 0.f;
        float a2x = 0.f, a2y = 0.f, a3x = 0.f, a3y = 0.f;
        #pragma unroll 4
        for (int q = 0; q < DH; q++) {
            float2 wv = *(const float2*)&W2[q * GH + 2 * t];
            float h0 = sh[4 * w + 0][q];
            float h1 = sh[4 * w + 1][q];
            float h2 = sh[4 * w + 2][q];
            float h3 = sh[4 * w + 3][q];
            a0x = fmaf(h0, wv.x, a0x); a0y = fmaf(h0, wv.y, a0y);
            a1x = fmaf(h1, wv.x, a1x); a1y = fmaf(h1, wv.y, a1y);
            a2x = fmaf(h2, wv.x, a2x); a2y = fmaf(h2, wv.y, a2y);
            a3x = fmaf(h3, wv.x, a3x); a3y = fmaf(h3, wv.y, a3y);
        }
        float2 bv = *(const float2*)&b2[2 * t];
        #pragma unroll
        for (int j = 0; j < 4; j++) {
            int n = base + 4 * w + j;
            if (n >= NN) break;
            float ax = (j == 0) ? a0x : (j == 1) ? a1x : (j == 2) ? a2x : a3x;
            float ay = (j == 0) ? a0y : (j == 1) ? a1y : (j == 2) ? a2y : a3y;
            float2 o;
            o.x = gelu_f(ax + bv.x);
            o.y = gelu_f(ay + bv.y);
            *(float2*)&g_m0[n * GH + 2 * t] = o;
        }
    }
}

// ---------------- SumGNN scatter: 8 lanes/edge, 4 edges/warp, segmented merge ----------------
template <int SRC>
__global__ __launch_bounds__(256) void k_scatter64() {
    const float* m = SRC ? g_m1 : g_m0;
    int tid = blockIdx.x * blockDim.x + threadIdx.x;
    if (tid >= NE * 8) return;
    int e = tid >> 3, ql = tid & 7;
    int2 sd = g_sdS[e];
    int s = sd.x, d = sd.y;
    const float4* m4 = (const float4*)m;
    float4 v0 = m4[s * 16 + ql];
    float4 v1 = m4[s * 16 + 8 + ql];
    unsigned lane = threadIdx.x & 31;

    #pragma unroll
    for (int off = 8; off <= 16; off <<= 1) {
        int od = __shfl_down_sync(0xffffffffu, d, off);
        float4 o0 = shfl_down4(v0, off);
        float4 o1 = shfl_down4(v1, off);
        bool ok = (lane + off < 32) && (od == d);
        if (ok) {
            v0.x += o0.x; v0.y += o0.y; v0.z += o0.z; v0.w += o0.w;
            v1.x += o1.x; v1.y += o1.y; v1.z += o1.z; v1.w += o1.w;
        }
    }
    int pd = __shfl_up_sync(0xffffffffu, d, 8);
    if (lane < 8 || pd != d) {
        float* base = &g_agg64[d * GH];
        red4(base + 4 * ql, v0);
        red4(base + 32 + 4 * ql, v1);
    }
}

// ---------------- SumGNN update: weights via L1 (__ldg), tiles in smem ----------------
template <int SRC>
__global__ __launch_bounds__(256) void k_update(const float* __restrict__ Ws,
                                                const float* __restrict__ Wn)
{
    const float* min_ = SRC ? g_m1 : g_m0;
    float* mout       = SRC ? g_m0 : g_m1;
    __shared__ float sm[32][66];
    __shared__ float sa[32][66];
    int tid = threadIdx.x;
    int base = blockIdx.x * 32;

    for (int i = tid; i < 32 * (GH / 2); i += 256) {
        int nl = i >> 5, c2 = i & 31;
        int n = base + nl;
        float2 av = make_float2(0.f, 0.f);
        float2 mv = make_float2(0.f, 0.f);
        if (n < NN) {
            av = *(const float2*)&g_agg64[n * GH + 2 * c2];
            mv = *(const float2*)&min_[n * GH + 2 * c2];
            *(float2*)&g_agg64[n * GH + 2 * c2] = make_float2(0.f, 0.f);
        }
        sm[nl][2 * c2] = mv.x; sm[nl][2 * c2 + 1] = mv.y;
        sa[nl][2 * c2] = av.x; sa[nl][2 * c2 + 1] = av.y;
    }
    __syncthreads();

    int nt = tid >> 3;
    int ob = 8 * (tid & 7);
    float a[8] = {0.f, 0.f, 0.f, 0.f, 0.f, 0.f, 0.f, 0.f};
    #pragma unroll 2
    for (int q = 0; q < GH; q++) {
        float mv = sm[nt][q], av = sa[nt][q];
        float4 ws0 = __ldg((const float4*)&Ws[q * GH + ob]);
        float4 ws1 = __ldg((const float4*)&Ws[q * GH + ob + 4]);
        float4 wn0 = __ldg((const float4*)&Wn[q * GH + ob]);
        float4 wn1 = __ldg((const float4*)&Wn[q * GH + ob + 4]);
        a[0] += mv * ws0.x + av * wn0.x; a[1] += mv * ws0.y + av * wn0.y;
        a[2] += mv * ws0.z + av * wn0.z; a[3] += mv * ws0.w + av * wn0.w;
        a[4] += mv * ws1.x + av * wn1.x; a[5] += mv * ws1.y + av * wn1.y;
        a[6] += mv * ws1.z + av * wn1.z; a[7] += mv * ws1.w + av * wn1.w;
    }
    int n = base + nt;
    if (n < NN) {
        float4 o0, o1;
        o0.x = gelu_f(a[0]); o0.y = gelu_f(a[1]); o0.z = gelu_f(a[2]); o0.w = gelu_f(a[3]);
        o1.x = gelu_f(a[4]); o1.y = gelu_f(a[5]); o1.z = gelu_f(a[6]); o1.w = gelu_f(a[7]);
        *(float4*)&mout[n * GH + ob] = o0;
        *(float4*)&mout[n * GH + ob + 4] = o1;
    }
}

// ---------------- theta -> per-node (cos, sin, rdeg) ----------------
__global__ __launch_bounds__(256) void k_theta(
    const float* __restrict__ w2, const float* __restrict__ b2)
{
    int warp = threadIdx.x >> 5;
    int lane = threadIdx.x & 31;
    int n = blockIdx.x * 8 + warp;
    if (n >= NN) return;
    float acc = g_m0[n * GH + lane] * w2[lane] + g_m0[n * GH + 32 + lane] * w2[32 + lane];
    #pragma unroll
    for (int off = 16; off > 0; off >>= 1)
        acc += __shfl_xor_sync(0xFFFFFFFFu, acc, off);
    if (lane == 0) {
        float t = tanhf(acc + b2[0]);
        float ang = t * 6.283185307179586f;
        float s, c;
        sincosf(ang, &s, &c);
        float rd = rsqrtf((float)g_cnt[n] + 1.0f);
        g_node[n] = make_float4(c, s, rd, 0.f);
    }
}

// ---------------- rotate: y[n] = rdeg_n * R(theta_n) * xs[n]. 8 lanes/node ----------------
// Lane q<4 computes d=0 rows: y0 = r*(c*x0 - s*x1); q>=4 d=1: y1 = r*(s*x0 + c*x1).
__global__ __launch_bounds__(256) void k_rotate() {
    int tid = blockIdx.x * blockDim.x + threadIdx.x;
    if (tid >= NN * 8) return;
    int n = tid >> 3, q = tid & 7;
    float4 nd = g_node[n];
    const float4* xs4 = (const float4*)g_x0;
    float4 v = xs4[n * 8 + q];
    float4 other = shfl_xor4(v, 4);
    float sb = (q < 4) ? -nd.y : nd.y;
    float4 y;
    y.x = nd.z * fmaf(nd.x, v.x, sb * other.x);
    y.y = nd.z * fmaf(nd.x, v.y, sb * other.y);
    y.z = nd.z * fmaf(nd.x, v.z, sb * other.z);
    y.w = nd.z * fmaf(nd.x, v.w, sb * other.w);
    ((float4*)g_y)[n * 8 + q] = y;
}

// ---------------- diffusion scatter: pure segment-sum of y rows ----------------
// 8 lanes/edge x float4 = one 128B line per edge in ONE instruction.
__global__ __launch_bounds__(256) void k_diff_scatter() {
    int tid = blockIdx.x * blockDim.x + threadIdx.x;
    if (tid >= NE * 8) return;
    int e = tid >> 3, ql = tid & 7;
    int2 sd = g_sdS[e];
    int s = sd.x, d = sd.y;
    float4 v = ((const float4*)g_y)[s * 8 + ql];
    unsigned lane = threadIdx.x & 31;

    #pragma unroll
    for (int off = 8; off <= 16; off <<= 1) {
        int od = __shfl_down_sync(0xffffffffu, d, off);
        float4 o = shfl_down4(v, off);
        bool ok = (lane + off < 32) && (od == d);
        if (ok) {
            v.x += o.x; v.y += o.y; v.z += o.z; v.w += o.w;
        }
    }
    int pd = __shfl_up_sync(0xffffffffu, d, 8);
    if (lane < 8 || pd != d) {
        red4(&g_agg32[d * DH + 4 * ql], v);
    }
}

// ---------------- diffusion update: agg' = rdeg_d*R(-theta_d)*agg; xs -= gelu((xs-agg')@W) ----------------
__global__ __launch_bounds__(256) void k_diff_update(const float* __restrict__ W) {
    __shared__ float sW[HH * HH];
    __shared__ float sxs[8][DH];
    __shared__ float sag[8][DH];
    __shared__ float4 snode[8];
    int base = blockIdx.x * 8;
    if (threadIdx.x < HH * HH) sW[threadIdx.x] = W[threadIdx.x];
    if (threadIdx.x < 8) {
        int n = min(base + (int)threadIdx.x, NN - 1);
        snode[threadIdx.x] = g_node[n];
    }
    {
        int i = threadIdx.x;
        int nl = i >> 5, c = i & 31;
        int n = base + nl;
        sxs[nl][c] = (n < NN) ? g_x0[n * DH + c] : 0.0f;
        sag[nl][c] = (n < NN) ? g_agg32[n * DH + c] : 0.0f;
    }
    __syncthreads();
    // transform agg: for col k (0..15): [a0;a1] -> rd*[c*a0+s*a1; -s*a0+c*a1]
    float tval;
    {
        int i = threadIdx.x;
        int nl = i >> 5, idx = i & 31;
        int dd = idx >> 4, k = idx & 15;
        float4 nd = snode[nl];
        float a0 = sag[nl][k], a1 = sag[nl][16 + k];
        tval = (dd == 0) ? nd.z * fmaf(nd.x, a0, nd.y * a1)
                         : nd.z * fmaf(nd.x, a1, -nd.y * a0);
    }
    __syncthreads();
    {
        int i = threadIdx.x;
        int nl = i >> 5, idx = i & 31;
        sag[nl][idx] = tval;
    }
    __syncthreads();
    {
        int i = threadIdx.x;
        int nl = i >> 5, idx = i & 31;
        int dd = idx >> 4, k = idx & 15;
        float acc = 0.f;
        #pragma unroll
        for (int h = 0; h < HH; h++) {
            float lx = sxs[nl][dd * HH + h] - sag[nl][dd * HH + h];
            acc = fmaf(lx, sW[h * HH + k], acc);
        }
        int n = base + nl;
        if (n < NN) {
            g_x0[n * DH + idx] = sxs[nl][idx] - gelu_f(acc);
            g_agg32[n * DH + idx] = 0.0f;
        }
    }
}

// ---------------- output: smem-staged, 32 nodes/block, 320 threads ----------------
__global__ __launch_bounds__(320) void k_out(
    const float* __restrict__ W_out, const float* __restrict__ b_out,
    float* __restrict__ out)
{
    __shared__ __align__(16) float sxs[32][36];
    __shared__ float sW[DH * NOUT];
    __shared__ float sb[NOUT];
    int base = blockIdx.x * 32;
    if (threadIdx.x < DH * NOUT) sW[threadIdx.x] = W_out[threadIdx.x];
    if (threadIdx.x < NOUT) sb[threadIdx.x] = b_out[threadIdx.x];
    if (threadIdx.x < 256) {
        int nl = threadIdx.x >> 3, c = (threadIdx.x & 7) * 4;
        int n = min(base + nl, NN - 1);
        *(float4*)&sxs[nl][c] = *(const float4*)&g_x0[n * DH + c];
    }
    __syncthreads();
    int nl = threadIdx.x / NOUT;
    int o = threadIdx.x - nl * NOUT;
    if (nl < 32) {
        int n = base + nl;
        if (n < NN) {
            float acc = sb[o];
            #pragma unroll
            for (int i = 0; i < DH; i++) acc = fmaf(sxs[nl][i], sW[i * NOUT + o], acc);
            out[n * NOUT + o] = acc;
        }
    }
}

// ---------------- launch ----------------
extern "C" void kernel_launch(void* const* d_in, const int* in_sizes, int n_in,
                              void* d_out, int out_size) {
    int i_x = 0, i_ei = 1;
    for (int i = 0; i < n_in; i++) {
        if (in_sizes[i] == NN * FIN) i_x = i;
        if (in_sizes[i] == 2 * NE)   i_ei = i;
    }
    const float* x  = (const float*)d_in[i_x];
    const void*  ei = d_in[i_ei];
    const float* W_in   = (const float*)d_in[2];
    const float* b_in   = (const float*)d_in[3];
    const float* emb1_W = (const float*)d_in[4];
    const float* emb1_b = (const float*)d_in[5];
    const float* Ws1    = (const float*)d_in[6];
    const float* Wn1    = (const float*)d_in[7];
    const float* Ws2    = (const float*)d_in[8];
    const float* Wn2    = (const float*)d_in[9];
    const float* emb2_W = (const float*)d_in[10];
    const float* emb2_b = (const float*)d_in[11];
    const float* W_diff = (const float*)d_in[12];
    const float* W_out  = (const float*)d_in[13];
    const float* b_out  = (const float*)d_in[14];
    float* out = (float*)d_out;

    k_init<<<(NN + 255) / 256, 256>>>((const unsigned int*)ei);            // 0
    k_prep<<<(NE + 255) / 256, 256>>>(ei);                                  // 1
    k_scan1<<<NBLK, 256>>>();                                               // 2
    k_embed<<<(NN + 31) / 32, 256>>>(x, W_in, b_in, emb1_W, emb1_b);        // 3 (profiled)
    k_scan2<<<1, 512>>>();                                                  // 4
    k_scan3<<<NBLK, 256>>>();                                               // 5
    k_place<<<(NE + 255) / 256, 256>>>();                                   // 6

    k_scatter64<0><<<(NE * 8 + 255) / 256, 256>>>();                        // 7
    k_update<0><<<(NN + 31) / 32, 256>>>(Ws1, Wn1);                         // 8   m0 -> m1
    k_scatter64<1><<<(NE * 8 + 255) / 256, 256>>>();                        // 9
    k_update<1><<<(NN + 31) / 32, 256>>>(Ws2, Wn2);                         // 10  m1 -> m0

    k_theta<<<(NN + 7) / 8, 256>>>(emb2_W, emb2_b);                         // 11

    k_rotate<<<(NN * 8 + 255) / 256, 256>>>();                              // 12
    k_diff_scatter<<<(NE * 8 + 255) / 256, 256>>>();                        // 13
    k_diff_update<<<(NN + 7) / 8, 256>>>(W_diff);                           // 14
    k_rotate<<<(NN * 8 + 255) / 256, 256>>>();                              // 15
    k_diff_scatter<<<(NE * 8 + 255) / 256, 256>>>();                        // 16
    k_diff_update<<<(NN + 7) / 8, 256>>>(W_diff + HH * HH);                 // 17

    k_out<<<(NN * NOUT + 31 * NOUT - 1) / (32 * NOUT), 320>>>(W_out, b_out, out); // 18
}

// round 16
// speedup vs baseline: 1.5379x; 1.5379x over previous
#include <cuda_runtime.h>
#include <cuda_bf16.h>

#define NN 100000
#define NE 1600000
#define FIN 128
#define DH 32        // D*H
#define GH 64
#define HH 16
#define NOUT 10
#define NBLK 391     // (NN+255)/256

// ---------------- scratch (device globals; zero-initialized at module load) ----------------
__device__ __align__(16) float g_x0[NN * DH];         // h / xs (in-place)
__device__ __align__(16) float g_y[NN * DH];          // rdeg_s * R(theta_s) * xs  (per layer)
__device__ __align__(16) float g_m0[NN * GH];
__device__ __align__(16) float g_m1[NN * GH];
__device__ __align__(16) float g_agg64[NN * GH];      // zero at launch start (consumers re-zero)
__device__ __align__(16) float g_agg32[NN * DH];      // same invariant
__device__ __align__(16) float4 g_node[NN];           // (cos, sin, rdeg, 0)
__device__ int g_src[NE];                              // unsorted
__device__ int g_dst[NE];
__device__ __align__(8) int2 g_sdS[NE];                // (src,dst) sorted by dst
__device__ int g_cnt[NN];
__device__ int g_rowptr[NN];
__device__ int g_cursor[NN];
__device__ int g_bsum[NBLK];
__device__ int g_bsumx[NBLK];
__device__ int g_idx64;

// ---------------- helpers ----------------
__device__ __forceinline__ float gelu_f(float v) {
    const float c = 0.7978845608028654f;
    float t = tanhf(c * (v + 0.044715f * v * v * v));
    return 0.5f * v * (1.0f + t);
}

__device__ __forceinline__ void red4(float* p, float4 v) {
    atomicAdd(reinterpret_cast<float4*>(p), v);
}

__device__ __forceinline__ float4 shfl_down4(float4 v, int off) {
    float4 r;
    r.x = __shfl_down_sync(0xffffffffu, v.x, off);
    r.y = __shfl_down_sync(0xffffffffu, v.y, off);
    r.z = __shfl_down_sync(0xffffffffu, v.z, off);
    r.w = __shfl_down_sync(0xffffffffu, v.w, off);
    return r;
}

// ---------------- init: zero degree counts; probe edge dtype ----------------
__global__ void k_init(const unsigned int* __restrict__ ei_words) {
    int i = blockIdx.x * blockDim.x + threadIdx.x;
    if (i < NN) g_cnt[i] = 0;
    if (i == 0) {
        int is64 = 1;
        for (int k = 0; k < 256; k++)
            if (ei_words[2 * k + 1] != 0u) { is64 = 0; break; }
        g_idx64 = is64;
    }
}

// ---------------- prep: decode indices, count in-degree ----------------
__global__ void k_prep(const void* __restrict__ ei) {
    int e = blockIdx.x * blockDim.x + threadIdx.x;
    if (e >= NE) return;
    int s, d;
    if (g_idx64) {
        const long long* p = (const long long*)ei;
        s = (int)p[e]; d = (int)p[NE + e];
    } else {
        const int* p = (const int*)ei;
        s = p[e]; d = p[NE + e];
    }
    s = min(max(s, 0), NN - 1);
    d = min(max(d, 0), NN - 1);
    g_src[e] = s;
    g_dst[e] = d;
    atomicAdd(&g_cnt[d], 1);
}

// ---------------- counting-sort scans ----------------
__global__ void k_scan1() {
    __shared__ int sm[256];
    int t = threadIdx.x;
    int i = blockIdx.x * 256 + t;
    int v = (i < NN) ? g_cnt[i] : 0;
    sm[t] = v;
    __syncthreads();
    for (int off = 1; off < 256; off <<= 1) {
        int x = (t >= off) ? sm[t - off] : 0;
        __syncthreads();
        sm[t] += x;
        __syncthreads();
    }
    if (i < NN) g_rowptr[i] = sm[t] - v;
    if (t == 255) g_bsum[blockIdx.x] = sm[255];
}

__global__ void k_scan2() {
    __shared__ int sm[512];
    int t = threadIdx.x;
    int v = (t < NBLK) ? g_bsum[t] : 0;
    sm[t] = v;
    __syncthreads();
    for (int off = 1; off < 512; off <<= 1) {
        int x = (t >= off) ? sm[t - off] : 0;
        __syncthreads();
        sm[t] += x;
        __syncthreads();
    }
    if (t < NBLK) g_bsumx[t] = sm[t] - v;
}

__global__ void k_scan3() {
    int i = blockIdx.x * blockDim.x + threadIdx.x;
    if (i < NN) {
        int rp = g_rowptr[i] + g_bsumx[i >> 8];
        g_cursor[i] = rp;
    }
}

__global__ void k_place() {
    int e = blockIdx.x * blockDim.x + threadIdx.x;
    if (e >= NE) return;
    int d = g_dst[e];
    int pos = atomicAdd(&g_cursor[d], 1);
    g_sdS[pos] = make_int2(g_src[e], d);
}

// ---------------- embed v3: 4 nodes/warp, 32 nodes/block ----------------
__global__ __launch_bounds__(256) void k_embed(
    const float* __restrict__ x, const float* __restrict__ W_in,
    const float* __restrict__ b_in, const float* __restrict__ W2,
    const float* __restrict__ b2)
{
    __shared__ float sx[32][FIN];
    __shared__ float sh[32][DH + 1];
    int tid = threadIdx.x;
    int base = blockIdx.x * 32;

    {
        int nl = tid >> 3;
        int nc = min(base + nl, NN - 1);
        const float4* xr = (const float4*)(x + (size_t)nc * FIN);
        float4* sxr = (float4*)&sx[nl][(tid & 7) * 16];
        #pragma unroll
        for (int j = 0; j < 4; j++) sxr[j] = xr[(tid & 7) * 4 + j];
    }
    __syncthreads();

    int w = tid >> 5;
    int t = tid & 31;
    {
        float acc0 = 0.f, acc1 = 0.f, acc2 = 0.f, acc3 = 0.f;
        #pragma unroll 4
        for (int k = 0; k < FIN; k++) {
            float wv = W_in[k * DH + t];
            acc0 = fmaf(sx[4 * w + 0][k], wv, acc0);
            acc1 = fmaf(sx[4 * w + 1][k], wv, acc1);
            acc2 = fmaf(sx[4 * w + 2][k], wv, acc2);
            acc3 = fmaf(sx[4 * w + 3][k], wv, acc3);
        }
        float bv = b_in[t];
        acc0 += bv; acc1 += bv; acc2 += bv; acc3 += bv;
        sh[4 * w + 0][t] = acc0;
        sh[4 * w + 1][t] = acc1;
        sh[4 * w + 2][t] = acc2;
        sh[4 * w + 3][t] = acc3;
        #pragma unroll
        for (int j = 0; j < 4; j++) {
            int n = base + 4 * w + j;
            float v = (j == 0) ? acc0 : (j == 1) ? acc1 : (j == 2) ? acc2 : acc3;
            if (n < NN) g_x0[n * DH + t] = v;
        }
    }
    __syncthreads();

    {
        float a0x = 0.f, a0y = 0.f, a1x = 0.f, a1y = 0.f;
        float a2x = 0.f, a2y = 0.f, a3x = 0.f, a3y = 0.f;
        #pragma unroll 4
        for (int q = 0; q < DH; q++) {
            float2 wv = *(const float2*)&W2[q * GH + 2 * t];
            float h0 = sh[4 * w + 0][q];
            float h1 = sh[4 * w + 1][q];
            float h2 = sh[4 * w + 2][q];
            float h3 = sh[4 * w + 3][q];
            a0x = fmaf(h0, wv.x, a0x); a0y = fmaf(h0, wv.y, a0y);
            a1x = fmaf(h1, wv.x, a1x); a1y = fmaf(h1, wv.y, a1y);
            a2x = fmaf(h2, wv.x, a2x); a2y = fmaf(h2, wv.y, a2y);
            a3x = fmaf(h3, wv.x, a3x); a3y = fmaf(h3, wv.y, a3y);
        }
        float2 bv = *(const float2*)&b2[2 * t];
        #pragma unroll
        for (int j = 0; j < 4; j++) {
            int n = base + 4 * w + j;
            if (n >= NN) break;
            float ax = (j == 0) ? a0x : (j == 1) ? a1x : (j == 2) ? a2x : a3x;
            float ay = (j == 0) ? a0y : (j == 1) ? a1y : (j == 2) ? a2y : a3y;
            float2 o;
            o.x = gelu_f(ax + bv.x);
            o.y = gelu_f(ay + bv.y);
            *(float2*)&g_m0[n * GH + 2 * t] = o;
        }
    }
}

// ---------------- SumGNN scatter: 8 lanes/edge, 4 edges/warp, segmented merge ----------------
template <int SRC>
__global__ __launch_bounds__(256) void k_scatter64() {
    const float* m = SRC ? g_m1 : g_m0;
    int tid = blockIdx.x * blockDim.x + threadIdx.x;
    if (tid >= NE * 8) return;
    int e = tid >> 3, ql = tid & 7;
    int2 sd = g_sdS[e];
    int s = sd.x, d = sd.y;
    const float4* m4 = (const float4*)m;
    float4 v0 = m4[s * 16 + ql];
    float4 v1 = m4[s * 16 + 8 + ql];
    unsigned lane = threadIdx.x & 31;

    #pragma unroll
    for (int off = 8; off <= 16; off <<= 1) {
        int od = __shfl_down_sync(0xffffffffu, d, off);
        float4 o0 = shfl_down4(v0, off);
        float4 o1 = shfl_down4(v1, off);
        bool ok = (lane + off < 32) && (od == d);
        if (ok) {
            v0.x += o0.x; v0.y += o0.y; v0.z += o0.z; v0.w += o0.w;
            v1.x += o1.x; v1.y += o1.y; v1.z += o1.z; v1.w += o1.w;
        }
    }
    int pd = __shfl_up_sync(0xffffffffu, d, 8);
    if (lane < 8 || pd != d) {
        float* base = &g_agg64[d * GH];
        red4(base + 4 * ql, v0);
        red4(base + 32 + 4 * ql, v1);
    }
}

// ---------------- SumGNN update: weights via L1 (__ldg), tiles in smem ----------------
template <int SRC>
__global__ __launch_bounds__(256) void k_update(const float* __restrict__ Ws,
                                                const float* __restrict__ Wn)
{
    const float* min_ = SRC ? g_m1 : g_m0;
    float* mout       = SRC ? g_m0 : g_m1;
    __shared__ float sm[32][66];
    __shared__ float sa[32][66];
    int tid = threadIdx.x;
    int base = blockIdx.x * 32;

    for (int i = tid; i < 32 * (GH / 2); i += 256) {
        int nl = i >> 5, c2 = i & 31;
        int n = base + nl;
        float2 av = make_float2(0.f, 0.f);
        float2 mv = make_float2(0.f, 0.f);
        if (n < NN) {
            av = *(const float2*)&g_agg64[n * GH + 2 * c2];
            mv = *(const float2*)&min_[n * GH + 2 * c2];
            *(float2*)&g_agg64[n * GH + 2 * c2] = make_float2(0.f, 0.f);
        }
        sm[nl][2 * c2] = mv.x; sm[nl][2 * c2 + 1] = mv.y;
        sa[nl][2 * c2] = av.x; sa[nl][2 * c2 + 1] = av.y;
    }
    __syncthreads();

    int nt = tid >> 3;
    int ob = 8 * (tid & 7);
    float a[8] = {0.f, 0.f, 0.f, 0.f, 0.f, 0.f, 0.f, 0.f};
    #pragma unroll 2
    for (int q = 0; q < GH; q++) {
        float mv = sm[nt][q], av = sa[nt][q];
        float4 ws0 = __ldg((const float4*)&Ws[q * GH + ob]);
        float4 ws1 = __ldg((const float4*)&Ws[q * GH + ob + 4]);
        float4 wn0 = __ldg((const float4*)&Wn[q * GH + ob]);
        float4 wn1 = __ldg((const float4*)&Wn[q * GH + ob + 4]);
        a[0] += mv * ws0.x + av * wn0.x; a[1] += mv * ws0.y + av * wn0.y;
        a[2] += mv * ws0.z + av * wn0.z; a[3] += mv * ws0.w + av * wn0.w;
        a[4] += mv * ws1.x + av * wn1.x; a[5] += mv * ws1.y + av * wn1.y;
        a[6] += mv * ws1.z + av * wn1.z; a[7] += mv * ws1.w + av * wn1.w;
    }
    int n = base + nt;
    if (n < NN) {
        float4 o0, o1;
        o0.x = gelu_f(a[0]); o0.y = gelu_f(a[1]); o0.z = gelu_f(a[2]); o0.w = gelu_f(a[3]);
        o1.x = gelu_f(a[4]); o1.y = gelu_f(a[5]); o1.z = gelu_f(a[6]); o1.w = gelu_f(a[7]);
        *(float4*)&mout[n * GH + ob] = o0;
        *(float4*)&mout[n * GH + ob + 4] = o1;
    }
}

// ---------------- theta + layer-1 rotate: g_node AND g_y in one pass ----------------
__global__ __launch_bounds__(256) void k_theta(
    const float* __restrict__ w2, const float* __restrict__ b2)
{
    int warp = threadIdx.x >> 5;
    int lane = threadIdx.x & 31;
    int n = blockIdx.x * 8 + warp;
    if (n >= NN) return;
    float acc = g_m0[n * GH + lane] * w2[lane] + g_m0[n * GH + 32 + lane] * w2[32 + lane];
    #pragma unroll
    for (int off = 16; off > 0; off >>= 1)
        acc += __shfl_xor_sync(0xFFFFFFFFu, acc, off);
    // acc identical on all lanes after butterfly
    float t = tanhf(acc + b2[0]);
    float ang = t * 6.283185307179586f;
    float s, c;
    sincosf(ang, &s, &c);
    float rd = rsqrtf((float)g_cnt[n] + 1.0f);
    if (lane == 0) g_node[n] = make_float4(c, s, rd, 0.f);
    // rotate the node's x-row: lane<16 d=0: rd*(c*x0 - s*x1); lane>=16 d=1: rd*(s*x0 + c*x1)
    float xv = g_x0[n * DH + lane];
    float other = __shfl_xor_sync(0xffffffffu, xv, 16);
    float y = (lane < 16) ? rd * fmaf(c, xv, -s * other)
                          : rd * fmaf(c, xv,  s * other);
    g_y[n * DH + lane] = y;
}

// ---------------- diffusion scatter: pure segment-sum of y rows ----------------
__global__ __launch_bounds__(256) void k_diff_scatter() {
    int tid = blockIdx.x * blockDim.x + threadIdx.x;
    if (tid >= NE * 8) return;
    int e = tid >> 3, ql = tid & 7;
    int2 sd = g_sdS[e];
    int s = sd.x, d = sd.y;
    float4 v = ((const float4*)g_y)[s * 8 + ql];
    unsigned lane = threadIdx.x & 31;

    #pragma unroll
    for (int off = 8; off <= 16; off <<= 1) {
        int od = __shfl_down_sync(0xffffffffu, d, off);
        float4 o = shfl_down4(v, off);
        bool ok = (lane + off < 32) && (od == d);
        if (ok) {
            v.x += o.x; v.y += o.y; v.z += o.z; v.w += o.w;
        }
    }
    int pd = __shfl_up_sync(0xffffffffu, d, 8);
    if (lane < 8 || pd != d) {
        red4(&g_agg32[d * DH + 4 * ql], v);
    }
}

// ---------------- diffusion update; LAST==0 also emits next layer's y ----------------
// agg' = rdeg_d * R(-theta_d) * agg; xs -= gelu((xs - agg') @ W); zero agg.
template <int LAST>
__global__ __launch_bounds__(256) void k_diff_update(const float* __restrict__ W) {
    __shared__ float sW[HH * HH];
    __shared__ float sxs[8][DH];
    __shared__ float sag[8][DH];
    __shared__ float4 snode[8];
    int base = blockIdx.x * 8;
    if (threadIdx.x < HH * HH) sW[threadIdx.x] = W[threadIdx.x];
    if (threadIdx.x < 8) {
        int n = min(base + (int)threadIdx.x, NN - 1);
        snode[threadIdx.x] = g_node[n];
    }
    int i = threadIdx.x;
    int nl = i >> 5, idx = i & 31;
    int dd = idx >> 4, k = idx & 15;
    int n = base + nl;
    {
        sxs[nl][idx] = (n < NN) ? g_x0[n * DH + idx] : 0.0f;
        sag[nl][idx] = (n < NN) ? g_agg32[n * DH + idx] : 0.0f;
    }
    __syncthreads();
    // transform agg: col k: [a0;a1] -> rd*[c*a0 + s*a1; -s*a0 + c*a1]
    float tval;
    {
        float4 nd = snode[nl];
        float a0 = sag[nl][k], a1 = sag[nl][16 + k];
        tval = (dd == 0) ? nd.z * fmaf(nd.x, a0, nd.y * a1)
                         : nd.z * fmaf(nd.x, a1, -nd.y * a0);
    }
    __syncthreads();
    sag[nl][idx] = tval;
    __syncthreads();
    float xnew;
    {
        float acc = 0.f;
        #pragma unroll
        for (int h = 0; h < HH; h++) {
            float lx = sxs[nl][dd * HH + h] - sag[nl][dd * HH + h];
            acc = fmaf(lx, sW[h * HH + k], acc);
        }
        xnew = sxs[nl][idx] - gelu_f(acc);
        if (n < NN) {
            g_x0[n * DH + idx] = xnew;
            g_agg32[n * DH + idx] = 0.0f;
        }
    }
    if (!LAST) {
        // emit next layer's y = rd * R(theta) * xnew
        __syncthreads();
        sag[nl][idx] = xnew;       // reuse as xnew buffer
        __syncthreads();
        float4 nd = snode[nl];
        float other = sag[nl][idx ^ 16];
        float y = (dd == 0) ? nd.z * fmaf(nd.x, xnew, -nd.y * other)
                            : nd.z * fmaf(nd.x, xnew,  nd.y * other);
        if (n < NN) g_y[n * DH + idx] = y;
    }
}

// ---------------- output: smem-staged, 32 nodes/block, 320 threads ----------------
__global__ __launch_bounds__(320) void k_out(
    const float* __restrict__ W_out, const float* __restrict__ b_out,
    float* __restrict__ out)
{
    __shared__ __align__(16) float sxs[32][36];
    __shared__ float sW[DH * NOUT];
    __shared__ float sb[NOUT];
    int base = blockIdx.x * 32;
    if (threadIdx.x < DH * NOUT) sW[threadIdx.x] = W_out[threadIdx.x];
    if (threadIdx.x < NOUT) sb[threadIdx.x] = b_out[threadIdx.x];
    if (threadIdx.x < 256) {
        int nl = threadIdx.x >> 3, c = (threadIdx.x & 7) * 4;
        int n = min(base + nl, NN - 1);
        *(float4*)&sxs[nl][c] = *(const float4*)&g_x0[n * DH + c];
    }
    __syncthreads();
    int nl = threadIdx.x / NOUT;
    int o = threadIdx.x - nl * NOUT;
    if (nl < 32) {
        int n = base + nl;
        if (n < NN) {
            float acc = sb[o];
            #pragma unroll
            for (int i = 0; i < DH; i++) acc = fmaf(sxs[nl][i], sW[i * NOUT + o], acc);
            out[n * NOUT + o] = acc;
        }
    }
}

// ---------------- launch ----------------
extern "C" void kernel_launch(void* const* d_in, const int* in_sizes, int n_in,
                              void* d_out, int out_size) {
    int i_x = 0, i_ei = 1;
    for (int i = 0; i < n_in; i++) {
        if (in_sizes[i] == NN * FIN) i_x = i;
        if (in_sizes[i] == 2 * NE)   i_ei = i;
    }
    const float* x  = (const float*)d_in[i_x];
    const void*  ei = d_in[i_ei];
    const float* W_in   = (const float*)d_in[2];
    const float* b_in   = (const float*)d_in[3];
    const float* emb1_W = (const float*)d_in[4];
    const float* emb1_b = (const float*)d_in[5];
    const float* Ws1    = (const float*)d_in[6];
    const float* Wn1    = (const float*)d_in[7];
    const float* Ws2    = (const float*)d_in[8];
    const float* Wn2    = (const float*)d_in[9];
    const float* emb2_W = (const float*)d_in[10];
    const float* emb2_b = (const float*)d_in[11];
    const float* W_diff = (const float*)d_in[12];
    const float* W_out  = (const float*)d_in[13];
    const float* b_out  = (const float*)d_in[14];
    float* out = (float*)d_out;

    k_init<<<(NN + 255) / 256, 256>>>((const unsigned int*)ei);            // 0
    k_prep<<<(NE + 255) / 256, 256>>>(ei);                                  // 1
    k_scan1<<<NBLK, 256>>>();                                               // 2
    k_embed<<<(NN + 31) / 32, 256>>>(x, W_in, b_in, emb1_W, emb1_b);        // 3 (profiled)
    k_scan2<<<1, 512>>>();                                                  // 4
    k_scan3<<<NBLK, 256>>>();                                               // 5
    k_place<<<(NE + 255) / 256, 256>>>();                                   // 6

    k_scatter64<0><<<(NE * 8 + 255) / 256, 256>>>();                        // 7
    k_update<0><<<(NN + 31) / 32, 256>>>(Ws1, Wn1);                         // 8   m0 -> m1
    k_scatter64<1><<<(NE * 8 + 255) / 256, 256>>>();                        // 9
    k_update<1><<<(NN + 31) / 32, 256>>>(Ws2, Wn2);                         // 10  m1 -> m0

    k_theta<<<(NN + 7) / 8, 256>>>(emb2_W, emb2_b);                         // 11 (+ rotate L1)

    k_diff_scatter<<<(NE * 8 + 255) / 256, 256>>>();                        // 12
    k_diff_update<0><<<(NN + 7) / 8, 256>>>(W_diff);                        // 13 (+ rotate L2)
    k_diff_scatter<<<(NE * 8 + 255) / 256, 256>>>();                        // 14
    k_diff_update<1><<<(NN + 7) / 8, 256>>>(W_diff + HH * HH);              // 15

    k_out<<<(NN * NOUT + 31 * NOUT - 1) / (32 * NOUT), 320>>>(W_out, b_out, out); // 16
}